// round 5
// baseline (speedup 1.0000x reference)
#include <cuda_runtime.h>

// SSIM loss, fused single kernel, f32x2-packed separable 11x11 Gaussian conv.
// 64x32 tile (halo 5) in dynamic SMEM. Phase 1: halo load + clip. Phase 2:
// vertical conv of (x,y,xx,yy,xy), col-pair packed FFMA2. Phase 3: horizontal
// conv, 256 items x 8 output cols + packed SSIM + global mean reduction.

#define TW 64
#define TH 32
#define HALO 5
#define KS 11
#define HR 42             // halo rows = TH + 10
#define HC 74             // halo cols = TW + 10
#define SWX 76            // sx/sy row stride (floats)
#define S2  38            // sv2 row stride (u64; 19 granules odd -> conflict-free)
#define NPAIR 37          // packed col-pairs in halo width
#define SMEM_BYTES (5*TH*S2*8 + 2*HR*SWX*4 + 32)

typedef unsigned long long u64t;

__device__ double g_acc = 0.0;
__device__ unsigned int g_cnt = 0;

__device__ constexpr float GW[11] = {
    0.00102838f, 0.00759876f, 0.03600078f, 0.10936069f, 0.21300553f,
    0.26601173f,
    0.21300553f, 0.10936069f, 0.03600078f, 0.00759876f, 0.00102838f};

__device__ __forceinline__ u64t pk2(float lo, float hi) {
    u64t r; asm("mov.b64 %0,{%1,%2};" : "=l"(r) : "f"(lo), "f"(hi)); return r;
}
__device__ __forceinline__ void upk2(u64t v, float& lo, float& hi) {
    asm("mov.b64 {%0,%1},%2;" : "=f"(lo), "=f"(hi) : "l"(v));
}
__device__ __forceinline__ u64t fma2_(u64t a, u64t b, u64t c) {
    u64t d; asm("fma.rn.f32x2 %0,%1,%2,%3;" : "=l"(d) : "l"(a), "l"(b), "l"(c)); return d;
}
__device__ __forceinline__ u64t mul2_(u64t a, u64t b) {
    u64t d; asm("mul.rn.f32x2 %0,%1,%2;" : "=l"(d) : "l"(a), "l"(b)); return d;
}
__device__ __forceinline__ u64t add2_(u64t a, u64t b) {
    u64t d; asm("add.rn.f32x2 %0,%1,%2;" : "=l"(d) : "l"(a), "l"(b)); return d;
}
__device__ __forceinline__ u64t sub2_(u64t a, u64t b) {
    u64t d; asm("sub.rn.f32x2 %0,%1,%2;" : "=l"(d) : "l"(a), "l"(b)); return d;
}

__device__ __forceinline__ constexpr int WS(int j) { return j < 6 ? j : 10 - j; }

extern __shared__ __align__(16) unsigned char smem_raw[];

__global__ __launch_bounds__(256, 3)
void ssim_main_k(const float* __restrict__ A, const float* __restrict__ Bp,
                 float* __restrict__ out) {
    u64t*  sv2 = (u64t*)smem_raw;                       // [5][TH][S2]
    float* sx  = (float*)(smem_raw + 5 * TH * S2 * 8);  // [HR][SWX]
    float* sy  = sx + HR * SWX;                         // [HR][SWX]
    float* red = sy + HR * SWX;                         // [8]

    const int tid = threadIdx.x;
    const int tx0 = blockIdx.x * TW;
    const int ty0 = blockIdx.y * TH;
    const size_t base = (size_t)blockIdx.z * (512 * 512);

    u64t wq[6];
#pragma unroll
    for (int j = 0; j < 6; j++) wq[j] = pk2(GW[j], GW[j]);

    // -------- Phase 1: halo tile load, clip, zero outside -------------------
    const bool interior = (blockIdx.x != 0) && (blockIdx.x != 7) &&
                          (blockIdx.y != 0) && (blockIdx.y != 15);
    if (interior) {
        for (int i = tid; i < HR * HC; i += 256) {
            int r = i / HC, c = i - r * HC;
            size_t idx = base + (size_t)(ty0 + r - HALO) * 512 + (tx0 + c - HALO);
            sx[r * SWX + c] = __saturatef(__ldg(A + idx));
            sy[r * SWX + c] = __saturatef(__ldg(Bp + idx));
        }
    } else {
        for (int i = tid; i < HR * HC; i += 256) {
            int r = i / HC, c = i - r * HC;
            int gy = ty0 + r - HALO, gx = tx0 + c - HALO;
            float xv = 0.f, yv = 0.f;
            if ((unsigned)gy < 512u && (unsigned)gx < 512u) {
                size_t idx = base + (size_t)gy * 512 + gx;
                xv = __saturatef(__ldg(A + idx));
                yv = __saturatef(__ldg(Bp + idx));
            }
            sx[r * SWX + c] = xv;
            sy[r * SWX + c] = yv;
        }
    }
    __syncthreads();

    // -------- Phase 2: vertical conv, col-pair packed ------------------------
    // 296 items = 8 rowgroups (4 rows each) x 37 packed col-pairs
    for (int i = tid; i < 8 * NPAIR; i += 256) {
        const int g = i / NPAIR;
        const int k = i - NPAIR * g;
        const int r0 = g * 4;
        u64t ax[4] = {0,0,0,0}, ay[4] = {0,0,0,0};
        u64t axx[4] = {0,0,0,0}, ayy[4] = {0,0,0,0}, axy[4] = {0,0,0,0};
        const float* px = &sx[r0 * SWX + 2 * k];
        const float* py = &sy[r0 * SWX + 2 * k];
#pragma unroll
        for (int p = 0; p < 14; p++) {
            float2 xv = *(const float2*)(px + p * SWX);
            float2 yv = *(const float2*)(py + p * SWX);
            u64t X = pk2(xv.x, xv.y);
            u64t Y = pk2(yv.x, yv.y);
            u64t XX = mul2_(X, X);
            u64t YY = mul2_(Y, Y);
            u64t XY = mul2_(X, Y);
#pragma unroll
            for (int o = 0; o < 4; o++) {
                int j = p - o;
                if (j >= 0 && j < KS) {
                    u64t w = wq[WS(j)];
                    ax[o]  = fma2_(w, X,  ax[o]);
                    ay[o]  = fma2_(w, Y,  ay[o]);
                    axx[o] = fma2_(w, XX, axx[o]);
                    ayy[o] = fma2_(w, YY, ayy[o]);
                    axy[o] = fma2_(w, XY, axy[o]);
                }
            }
        }
#pragma unroll
        for (int o = 0; o < 4; o++) {
            int row = r0 + o;
            sv2[(0 * TH + row) * S2 + k] = ax[o];
            sv2[(1 * TH + row) * S2 + k] = ay[o];
            sv2[(2 * TH + row) * S2 + k] = axx[o];
            sv2[(3 * TH + row) * S2 + k] = ayy[o];
            sv2[(4 * TH + row) * S2 + k] = axy[o];
        }
    }
    __syncthreads();

    // -------- Phase 3: horizontal conv + SSIM, 256 items x 8 cols ------------
    float lsum = 0.f;
    {
        const int r  = tid >> 3;          // 0..31
        const int cg = tid & 7;           // 0..7
        const int m0 = 4 * cg;            // packed elems m0 .. m0+8 (<= 36)
        u64t acc[5][4];
#pragma unroll
        for (int ch = 0; ch < 5; ch++) {
            const u64t* rowp = &sv2[(ch * TH + r) * S2 + m0];
            u64t E[9];
            ulonglong2 q0 = *(const ulonglong2*)(rowp);
            ulonglong2 q1 = *(const ulonglong2*)(rowp + 2);
            ulonglong2 q2 = *(const ulonglong2*)(rowp + 4);
            ulonglong2 q3 = *(const ulonglong2*)(rowp + 6);
            E[0] = q0.x; E[1] = q0.y; E[2] = q1.x; E[3] = q1.y;
            E[4] = q2.x; E[5] = q2.y; E[6] = q3.x; E[7] = q3.y;
            E[8] = rowp[8];
            float flo[9], fhi[9];
#pragma unroll
            for (int t = 0; t < 9; t++) upk2(E[t], flo[t], fhi[t]);
            u64t O[8];
#pragma unroll
            for (int t = 0; t < 8; t++) O[t] = pk2(fhi[t], flo[t + 1]);
#pragma unroll
            for (int o = 0; o < 4; o++) {
                u64t a = mul2_(wq[WS(0)], E[o]);
#pragma unroll
                for (int j = 1; j < KS; j++) {
                    u64t v = (j & 1) ? O[o + (j - 1) / 2] : E[o + j / 2];
                    a = fma2_(wq[WS(j)], v, a);
                }
                acc[ch][o] = a;
            }
        }
        const u64t TWO = pk2(2.f, 2.f);
        const u64t C1q = pk2(1e-4f, 1e-4f);
        const u64t C2q = pk2(9e-4f, 9e-4f);
#pragma unroll
        for (int o = 0; o < 4; o++) {
            u64t mu1 = acc[0][o], mu2 = acc[1][o];
            u64t mu1sq = mul2_(mu1, mu1);
            u64t mu2sq = mul2_(mu2, mu2);
            u64t mu12  = mul2_(mu1, mu2);
            u64t s1  = sub2_(acc[2][o], mu1sq);
            u64t s2  = sub2_(acc[3][o], mu2sq);
            u64t s12 = sub2_(acc[4][o], mu12);
            u64t num = mul2_(fma2_(TWO, mu12, C1q), fma2_(TWO, s12, C2q));
            u64t den = mul2_(add2_(add2_(mu1sq, mu2sq), C1q),
                             add2_(add2_(s1, s2), C2q));
            float nlo, nhi, dlo, dhi;
            upk2(num, nlo, nhi);
            upk2(den, dlo, dhi);
            lsum += __fdividef(nlo, dlo) + __fdividef(nhi, dhi);
        }
    }

    // -------- Block reduce -> atomic; last block finalizes -------------------
#pragma unroll
    for (int off = 16; off; off >>= 1)
        lsum += __shfl_xor_sync(0xffffffffu, lsum, off);
    if ((tid & 31) == 0) red[tid >> 5] = lsum;
    __syncthreads();
    if (tid == 0) {
        float s = 0.f;
#pragma unroll
        for (int i = 0; i < 8; i++) s += red[i];
        atomicAdd(&g_acc, (double)s);
        __threadfence();
        unsigned int total = gridDim.x * gridDim.y * gridDim.z;
        unsigned int old = atomicAdd(&g_cnt, 1u);
        if (old == total - 1u) {
            double tot = atomicAdd(&g_acc, 0.0);
            out[0] = 1.0f - (float)(tot / 25165824.0);   // 32*3*512*512
            g_acc = 0.0;
            __threadfence();
            g_cnt = 0;
        }
    }
}

extern "C" void kernel_launch(void* const* d_in, const int* in_sizes, int n_in,
                              void* d_out, int out_size) {
    const float* A = (const float*)d_in[0];   // denoised
    const float* B = (const float*)d_in[1];   // clean
    float* out = (float*)d_out;

    cudaFuncSetAttribute(ssim_main_k,
                         cudaFuncAttributeMaxDynamicSharedMemorySize,
                         SMEM_BYTES);
    dim3 grid(512 / TW, 512 / TH, 32 * 3);    // (8, 16, 96)
    ssim_main_k<<<grid, 256, SMEM_BYTES>>>(A, B, out);
}

// round 6
// speedup vs baseline: 1.2940x; 1.2940x over previous
#include <cuda_runtime.h>

// SSIM loss, fused single kernel, f32x2-packed separable 11x11 Gaussian conv.
// 32x32 tile + halo 5 (static SMEM, 4 blocks/SM). Phase 1: halo load + clip.
// Phase 2: vertical conv of (x,y,xx,yy,xy), col-pair packed FFMA2.
// Phase 3: horizontal conv, 256 items x 2 packed outputs + packed SSIM +
// global mean reduction.

#define TW 32
#define TH 32
#define HALO 5
#define KS 11
#define HWD 42
#define SWX 48            // sx/sy row stride (floats)
#define S2  22            // sv2 row stride (u64 elems)

typedef unsigned long long u64t;

__device__ double g_acc = 0.0;
__device__ unsigned int g_cnt = 0;

__device__ constexpr float GW[11] = {
    0.00102838f, 0.00759876f, 0.03600078f, 0.10936069f, 0.21300553f,
    0.26601173f,
    0.21300553f, 0.10936069f, 0.03600078f, 0.00759876f, 0.00102838f};

__device__ __forceinline__ u64t pk2(float lo, float hi) {
    u64t r; asm("mov.b64 %0,{%1,%2};" : "=l"(r) : "f"(lo), "f"(hi)); return r;
}
__device__ __forceinline__ void upk2(u64t v, float& lo, float& hi) {
    asm("mov.b64 {%0,%1},%2;" : "=f"(lo), "=f"(hi) : "l"(v));
}
__device__ __forceinline__ u64t fma2_(u64t a, u64t b, u64t c) {
    u64t d; asm("fma.rn.f32x2 %0,%1,%2,%3;" : "=l"(d) : "l"(a), "l"(b), "l"(c)); return d;
}
__device__ __forceinline__ u64t mul2_(u64t a, u64t b) {
    u64t d; asm("mul.rn.f32x2 %0,%1,%2;" : "=l"(d) : "l"(a), "l"(b)); return d;
}
__device__ __forceinline__ u64t add2_(u64t a, u64t b) {
    u64t d; asm("add.rn.f32x2 %0,%1,%2;" : "=l"(d) : "l"(a), "l"(b)); return d;
}
__device__ __forceinline__ u64t sub2_(u64t a, u64t b) {
    u64t d; asm("sub.rn.f32x2 %0,%1,%2;" : "=l"(d) : "l"(a), "l"(b)); return d;
}

__device__ __forceinline__ constexpr int WS(int j) { return j < 6 ? j : 10 - j; }

__global__ __launch_bounds__(256, 4)
void ssim_main_k(const float* __restrict__ A, const float* __restrict__ Bp,
                 float* __restrict__ out) {
    __shared__ __align__(16) float sx[HWD][SWX];
    __shared__ __align__(16) float sy[HWD][SWX];
    __shared__ __align__(16) u64t  sv2[5][TH][S2];
    __shared__ float red[8];

    const int tid = threadIdx.x;
    const int tx0 = blockIdx.x * TW;
    const int ty0 = blockIdx.y * TH;
    const size_t base = (size_t)blockIdx.z * (512 * 512);

    u64t wq[6];
#pragma unroll
    for (int j = 0; j < 6; j++) wq[j] = pk2(GW[j], GW[j]);

    // -------- Phase 1: halo tile load, clip, zero outside -------------------
    const bool interior = (blockIdx.x != 0) && (blockIdx.x != 15) &&
                          (blockIdx.y != 0) && (blockIdx.y != 15);
    if (interior) {
#pragma unroll
        for (int i = tid; i < HWD * HWD; i += 256) {
            int r = i / HWD, c = i - r * HWD;
            size_t idx = base + (size_t)(ty0 + r - HALO) * 512 + (tx0 + c - HALO);
            sx[r][c] = __saturatef(__ldg(A + idx));
            sy[r][c] = __saturatef(__ldg(Bp + idx));
        }
    } else {
#pragma unroll
        for (int i = tid; i < HWD * HWD; i += 256) {
            int r = i / HWD, c = i - r * HWD;
            int gy = ty0 + r - HALO, gx = tx0 + c - HALO;
            float xv = 0.f, yv = 0.f;
            if ((unsigned)gy < 512u && (unsigned)gx < 512u) {
                size_t idx = base + (size_t)gy * 512 + gx;
                xv = __saturatef(__ldg(A + idx));
                yv = __saturatef(__ldg(Bp + idx));
            }
            sx[r][c] = xv;
            sy[r][c] = yv;
        }
    }
    __syncthreads();

    // -------- Phase 2: vertical conv, col-pair packed ------------------------
    // 168 items = 8 rowgroups (4 rows each) x 21 packed col-pairs
    if (tid < 168) {
        const int g = tid / 21;
        const int k = tid - 21 * g;
        const int r0 = g * 4;
        u64t ax[4] = {0,0,0,0}, ay[4] = {0,0,0,0};
        u64t axx[4] = {0,0,0,0}, ayy[4] = {0,0,0,0}, axy[4] = {0,0,0,0};
        const float* px = &sx[r0][2 * k];
        const float* py = &sy[r0][2 * k];
#pragma unroll
        for (int p = 0; p < 14; p++) {
            float2 xv = *(const float2*)(px + p * SWX);
            float2 yv = *(const float2*)(py + p * SWX);
            u64t X = pk2(xv.x, xv.y);
            u64t Y = pk2(yv.x, yv.y);
            u64t XX = mul2_(X, X);
            u64t YY = mul2_(Y, Y);
            u64t XY = mul2_(X, Y);
#pragma unroll
            for (int o = 0; o < 4; o++) {
                int j = p - o;
                if (j >= 0 && j < KS) {
                    u64t w = wq[WS(j)];
                    ax[o]  = fma2_(w, X,  ax[o]);
                    ay[o]  = fma2_(w, Y,  ay[o]);
                    axx[o] = fma2_(w, XX, axx[o]);
                    ayy[o] = fma2_(w, YY, ayy[o]);
                    axy[o] = fma2_(w, XY, axy[o]);
                }
            }
        }
#pragma unroll
        for (int o = 0; o < 4; o++) {
            int row = r0 + o;
            sv2[0][row][k] = ax[o];
            sv2[1][row][k] = ay[o];
            sv2[2][row][k] = axx[o];
            sv2[3][row][k] = ayy[o];
            sv2[4][row][k] = axy[o];
        }
    }
    __syncthreads();

    // -------- Phase 3: horizontal conv + SSIM, 256 items ---------------------
    // item = 1 row x 4 output cols (2 packed outputs); 32 rows x 8 colgroups
    float lsum = 0.f;
    {
        const int r  = tid >> 3;
        const int cg = tid & 7;
        const int m0 = 2 * cg;           // packed elems m0 .. m0+6
        u64t acc[5][2];
#pragma unroll
        for (int ch = 0; ch < 5; ch++) {
            const u64t* rowp = &sv2[ch][r][m0];
            u64t E[7];
            ulonglong2 q0 = *(const ulonglong2*)(rowp);
            ulonglong2 q1 = *(const ulonglong2*)(rowp + 2);
            ulonglong2 q2 = *(const ulonglong2*)(rowp + 4);
            E[0] = q0.x; E[1] = q0.y; E[2] = q1.x; E[3] = q1.y;
            E[4] = q2.x; E[5] = q2.y; E[6] = rowp[6];
            float flo[7], fhi[7];
#pragma unroll
            for (int t = 0; t < 7; t++) upk2(E[t], flo[t], fhi[t]);
            u64t O[6];
#pragma unroll
            for (int t = 0; t < 6; t++) O[t] = pk2(fhi[t], flo[t + 1]);
#pragma unroll
            for (int o = 0; o < 2; o++) {
                u64t a = mul2_(wq[WS(0)], E[o]);
#pragma unroll
                for (int j = 1; j < KS; j++) {
                    u64t v = (j & 1) ? O[o + (j - 1) / 2] : E[o + j / 2];
                    a = fma2_(wq[WS(j)], v, a);
                }
                acc[ch][o] = a;
            }
        }
        const u64t TWO = pk2(2.f, 2.f);
        const u64t C1q = pk2(1e-4f, 1e-4f);
        const u64t C2q = pk2(9e-4f, 9e-4f);
#pragma unroll
        for (int o = 0; o < 2; o++) {
            u64t mu1 = acc[0][o], mu2 = acc[1][o];
            u64t mu1sq = mul2_(mu1, mu1);
            u64t mu2sq = mul2_(mu2, mu2);
            u64t mu12  = mul2_(mu1, mu2);
            u64t s1  = sub2_(acc[2][o], mu1sq);
            u64t s2  = sub2_(acc[3][o], mu2sq);
            u64t s12 = sub2_(acc[4][o], mu12);
            u64t num = mul2_(fma2_(TWO, mu12, C1q), fma2_(TWO, s12, C2q));
            u64t den = mul2_(add2_(add2_(mu1sq, mu2sq), C1q),
                             add2_(add2_(s1, s2), C2q));
            float nlo, nhi, dlo, dhi;
            upk2(num, nlo, nhi);
            upk2(den, dlo, dhi);
            lsum += __fdividef(nlo, dlo) + __fdividef(nhi, dhi);
        }
    }

    // -------- Block reduce -> atomic; last block finalizes -------------------
#pragma unroll
    for (int off = 16; off; off >>= 1)
        lsum += __shfl_xor_sync(0xffffffffu, lsum, off);
    if ((tid & 31) == 0) red[tid >> 5] = lsum;
    __syncthreads();
    if (tid == 0) {
        float s = 0.f;
#pragma unroll
        for (int i = 0; i < 8; i++) s += red[i];
        atomicAdd(&g_acc, (double)s);
        __threadfence();
        unsigned int total = gridDim.x * gridDim.y * gridDim.z;
        unsigned int old = atomicAdd(&g_cnt, 1u);
        if (old == total - 1u) {
            double tot = atomicAdd(&g_acc, 0.0);
            out[0] = 1.0f - (float)(tot / 25165824.0);   // 32*3*512*512
            g_acc = 0.0;
            __threadfence();
            g_cnt = 0;
        }
    }
}

extern "C" void kernel_launch(void* const* d_in, const int* in_sizes, int n_in,
                              void* d_out, int out_size) {
    const float* A = (const float*)d_in[0];   // denoised
    const float* B = (const float*)d_in[1];   // clean
    float* out = (float*)d_out;

    dim3 grid(512 / TW, 512 / TH, 32 * 3);    // (16, 16, 96)
    ssim_main_k<<<grid, 256>>>(A, B, out);
}

// round 7
// speedup vs baseline: 1.4943x; 1.1548x over previous
#include <cuda_runtime.h>

// SSIM loss, fused single kernel, f32x2-packed separable 11x11 Gaussian conv.
// 4-channel reformulation: s=cx+cy, d=cx-cy; conv (s, d, s^2, d^2) only.
//   P=mu_s^2, Q=mu_d^2, A=E[s^2], B=E[d^2]:
//   num = ((P-Q)/2+C1) * ((A-B-P+Q)/2+C2)
//   den = ((P+Q)/2+C1) * ((A+B-P-Q)/2+C2)
// 32x32 tile + halo 5, static SMEM, FFMA2 packed columns throughout.

#define TW 32
#define TH 32
#define HALO 5
#define KS 11
#define HWD 42
#define SWX 48            // ss/sd row stride (floats)
#define S2  22            // sv2 row stride (u64 elems)

typedef unsigned long long u64t;

__device__ double g_acc = 0.0;
__device__ unsigned int g_cnt = 0;

__device__ constexpr float GW[11] = {
    0.00102838f, 0.00759876f, 0.03600078f, 0.10936069f, 0.21300553f,
    0.26601173f,
    0.21300553f, 0.10936069f, 0.03600078f, 0.00759876f, 0.00102838f};

__device__ __forceinline__ u64t pk2(float lo, float hi) {
    u64t r; asm("mov.b64 %0,{%1,%2};" : "=l"(r) : "f"(lo), "f"(hi)); return r;
}
__device__ __forceinline__ void upk2(u64t v, float& lo, float& hi) {
    asm("mov.b64 {%0,%1},%2;" : "=f"(lo), "=f"(hi) : "l"(v));
}
__device__ __forceinline__ u64t fma2_(u64t a, u64t b, u64t c) {
    u64t d; asm("fma.rn.f32x2 %0,%1,%2,%3;" : "=l"(d) : "l"(a), "l"(b), "l"(c)); return d;
}
__device__ __forceinline__ u64t mul2_(u64t a, u64t b) {
    u64t d; asm("mul.rn.f32x2 %0,%1,%2;" : "=l"(d) : "l"(a), "l"(b)); return d;
}
__device__ __forceinline__ u64t add2_(u64t a, u64t b) {
    u64t d; asm("add.rn.f32x2 %0,%1,%2;" : "=l"(d) : "l"(a), "l"(b)); return d;
}
__device__ __forceinline__ u64t sub2_(u64t a, u64t b) {
    u64t d; asm("sub.rn.f32x2 %0,%1,%2;" : "=l"(d) : "l"(a), "l"(b)); return d;
}

__device__ __forceinline__ constexpr int WS(int j) { return j < 6 ? j : 10 - j; }

__global__ __launch_bounds__(256, 4)
void ssim_main_k(const float* __restrict__ A, const float* __restrict__ Bp,
                 float* __restrict__ out) {
    __shared__ __align__(16) float ss[HWD][SWX];
    __shared__ __align__(16) float sd[HWD][SWX];
    __shared__ __align__(16) u64t  sv2[4][TH][S2];
    __shared__ float red[8];

    const int tid = threadIdx.x;
    const int tx0 = blockIdx.x * TW;
    const int ty0 = blockIdx.y * TH;
    const size_t base = (size_t)blockIdx.z * (512 * 512);

    u64t wq[6];
#pragma unroll
    for (int j = 0; j < 6; j++) wq[j] = pk2(GW[j], GW[j]);

    // -------- Phase 1: halo load, clip, form s=cx+cy, d=cx-cy ---------------
    const bool interior = (blockIdx.x != 0) && (blockIdx.x != 15) &&
                          (blockIdx.y != 0) && (blockIdx.y != 15);
    if (interior) {
#pragma unroll
        for (int i = tid; i < HWD * HWD; i += 256) {
            int r = i / HWD, c = i - r * HWD;
            size_t idx = base + (size_t)(ty0 + r - HALO) * 512 + (tx0 + c - HALO);
            float cx = __saturatef(__ldg(A + idx));
            float cy = __saturatef(__ldg(Bp + idx));
            ss[r][c] = cx + cy;
            sd[r][c] = cx - cy;
        }
    } else {
#pragma unroll
        for (int i = tid; i < HWD * HWD; i += 256) {
            int r = i / HWD, c = i - r * HWD;
            int gy = ty0 + r - HALO, gx = tx0 + c - HALO;
            float cx = 0.f, cy = 0.f;
            if ((unsigned)gy < 512u && (unsigned)gx < 512u) {
                size_t idx = base + (size_t)gy * 512 + gx;
                cx = __saturatef(__ldg(A + idx));
                cy = __saturatef(__ldg(Bp + idx));
            }
            ss[r][c] = cx + cy;
            sd[r][c] = cx - cy;
        }
    }
    __syncthreads();

    // -------- Phase 2: vertical conv of (s, d, s^2, d^2), col-pair packed ----
    // 168 items = 8 rowgroups (4 rows each) x 21 packed col-pairs
    if (tid < 168) {
        const int g = tid / 21;
        const int k = tid - 21 * g;
        const int r0 = g * 4;
        u64t as_[4] = {0,0,0,0}, ad_[4] = {0,0,0,0};
        u64t ass[4] = {0,0,0,0}, add_[4] = {0,0,0,0};
        const float* ps = &ss[r0][2 * k];
        const float* pd = &sd[r0][2 * k];
#pragma unroll
        for (int p = 0; p < 14; p++) {
            float2 sv = *(const float2*)(ps + p * SWX);
            float2 dv = *(const float2*)(pd + p * SWX);
            u64t S = pk2(sv.x, sv.y);
            u64t D = pk2(dv.x, dv.y);
            u64t SS = mul2_(S, S);
            u64t DD = mul2_(D, D);
#pragma unroll
            for (int o = 0; o < 4; o++) {
                int j = p - o;
                if (j >= 0 && j < KS) {
                    u64t w = wq[WS(j)];
                    as_[o]  = fma2_(w, S,  as_[o]);
                    ad_[o]  = fma2_(w, D,  ad_[o]);
                    ass[o]  = fma2_(w, SS, ass[o]);
                    add_[o] = fma2_(w, DD, add_[o]);
                }
            }
        }
#pragma unroll
        for (int o = 0; o < 4; o++) {
            int row = r0 + o;
            sv2[0][row][k] = as_[o];
            sv2[1][row][k] = ad_[o];
            sv2[2][row][k] = ass[o];
            sv2[3][row][k] = add_[o];
        }
    }
    __syncthreads();

    // -------- Phase 3: horizontal conv + SSIM, 256 items ---------------------
    // item = 1 row x 4 output cols (2 packed outputs); 32 rows x 8 colgroups
    float lsum = 0.f;
    {
        const int r  = tid >> 3;
        const int cg = tid & 7;
        const int m0 = 2 * cg;           // packed elems m0 .. m0+6
        u64t acc[4][2];
#pragma unroll
        for (int ch = 0; ch < 4; ch++) {
            const u64t* rowp = &sv2[ch][r][m0];
            u64t E[7];
            ulonglong2 q0 = *(const ulonglong2*)(rowp);
            ulonglong2 q1 = *(const ulonglong2*)(rowp + 2);
            ulonglong2 q2 = *(const ulonglong2*)(rowp + 4);
            E[0] = q0.x; E[1] = q0.y; E[2] = q1.x; E[3] = q1.y;
            E[4] = q2.x; E[5] = q2.y; E[6] = rowp[6];
            float flo[7], fhi[7];
#pragma unroll
            for (int t = 0; t < 7; t++) upk2(E[t], flo[t], fhi[t]);
            u64t O[6];
#pragma unroll
            for (int t = 0; t < 6; t++) O[t] = pk2(fhi[t], flo[t + 1]);
#pragma unroll
            for (int o = 0; o < 2; o++) {
                u64t a = mul2_(wq[WS(0)], E[o]);
#pragma unroll
                for (int j = 1; j < KS; j++) {
                    u64t v = (j & 1) ? O[o + (j - 1) / 2] : E[o + j / 2];
                    a = fma2_(wq[WS(j)], v, a);
                }
                acc[ch][o] = a;
            }
        }
        const u64t HALF = pk2(0.5f, 0.5f);
        const u64t C1q = pk2(1e-4f, 1e-4f);
        const u64t C2q = pk2(9e-4f, 9e-4f);
#pragma unroll
        for (int o = 0; o < 2; o++) {
            u64t mus = acc[0][o], mud = acc[1][o];
            u64t Aq  = acc[2][o], Bq  = acc[3][o];
            u64t P = mul2_(mus, mus);
            u64t Q = mul2_(mud, mud);
            u64t PQd = sub2_(P, Q);
            u64t PQs = add2_(P, Q);
            u64t ABd = sub2_(Aq, Bq);
            u64t ABs = add2_(Aq, Bq);
            u64t nl = fma2_(HALF, PQd, C1q);              // (P-Q)/2 + C1
            u64t nr = fma2_(HALF, sub2_(ABd, PQd), C2q);  // (A-B-P+Q)/2 + C2
            u64t dl = fma2_(HALF, PQs, C1q);              // (P+Q)/2 + C1
            u64t dr = fma2_(HALF, sub2_(ABs, PQs), C2q);  // (A+B-P-Q)/2 + C2
            u64t num = mul2_(nl, nr);
            u64t den = mul2_(dl, dr);
            float nlo, nhi, dlo, dhi;
            upk2(num, nlo, nhi);
            upk2(den, dlo, dhi);
            lsum += __fdividef(nlo, dlo) + __fdividef(nhi, dhi);
        }
    }

    // -------- Block reduce -> atomic; last block finalizes -------------------
#pragma unroll
    for (int off = 16; off; off >>= 1)
        lsum += __shfl_xor_sync(0xffffffffu, lsum, off);
    if ((tid & 31) == 0) red[tid >> 5] = lsum;
    __syncthreads();
    if (tid == 0) {
        float s = 0.f;
#pragma unroll
        for (int i = 0; i < 8; i++) s += red[i];
        atomicAdd(&g_acc, (double)s);
        __threadfence();
        unsigned int total = gridDim.x * gridDim.y * gridDim.z;
        unsigned int old = atomicAdd(&g_cnt, 1u);
        if (old == total - 1u) {
            double tot = atomicAdd(&g_acc, 0.0);
            out[0] = 1.0f - (float)(tot / 25165824.0);   // 32*3*512*512
            g_acc = 0.0;
            __threadfence();
            g_cnt = 0;
        }
    }
}

extern "C" void kernel_launch(void* const* d_in, const int* in_sizes, int n_in,
                              void* d_out, int out_size) {
    const float* A = (const float*)d_in[0];   // denoised
    const float* B = (const float*)d_in[1];   // clean
    float* out = (float*)d_out;

    dim3 grid(512 / TW, 512 / TH, 32 * 3);    // (16, 16, 96)
    ssim_main_k<<<grid, 256>>>(A, B, out);
}